// round 4
// baseline (speedup 1.0000x reference)
#include <cuda_runtime.h>
#include <math.h>
#include <stdint.h>

#define BATCH 128

// ----------------- scratch buffers -----------------
__device__ float d_c1[BATCH*96*55*55];
__device__ float d_p1[BATCH*96*27*27];
__device__ float d_l1[BATCH*96*27*27];
__device__ float d_c2[BATCH*256*27*27];
__device__ float d_p2[BATCH*256*13*13];
__device__ float d_l2[BATCH*256*13*13];
__device__ float d_c3[BATCH*384*13*13];
__device__ float d_c4[BATCH*384*13*13];
__device__ float d_c5[BATCH*256*13*13];
__device__ float d_feat[BATCH*9216];
__device__ float d_h1[BATCH*4096];
__device__ float d_h2[BATCH*4096];
__device__ float d_out0[BATCH*100];
__device__ float d_g2[BATCH*4096];
__device__ float d_g1[BATCH*4096];
__device__ float d_sm[BATCH*36];
__device__ float d_mask[BATCH*36];
__device__ float d_featm[BATCH*9216];
__device__ float d_h1b[BATCH*4096];
__device__ float d_h2b[BATCH*4096];
__device__ float d_outb[BATCH*100];
__device__ float d_clsb[BATCH];
__device__ float d_clsa[BATCH];
__device__ float d_w6r[4096*36];
__device__ float d_w7t[4096*4096];
__device__ float d_part[4*BATCH*4096];

// ----------------- tf32 helpers -----------------
__device__ __forceinline__ float2 split_tf32(float v) {
    unsigned h, l;
    asm("cvt.rna.tf32.f32 %0, %1;" : "=r"(h) : "f"(v));
    float hf = __uint_as_float(h);
    asm("cvt.rna.tf32.f32 %0, %1;" : "=r"(l) : "f"(v - hf));
    float2 r; r.x = hf; r.y = __uint_as_float(l);
    return r;
}
__device__ __forceinline__ void mma8(float* c, const uint32_t* a, const uint32_t* b) {
    asm volatile(
        "mma.sync.aligned.m16n8k8.row.col.f32.tf32.tf32.f32 "
        "{%0,%1,%2,%3}, {%4,%5,%6,%7}, {%8,%9}, {%0,%1,%2,%3};"
        : "+f"(c[0]), "+f"(c[1]), "+f"(c[2]), "+f"(c[3])
        : "r"(a[0]), "r"(a[1]), "r"(a[2]), "r"(a[3]), "r"(b[0]), "r"(b[1]));
}

// smem layout: float2 (hi,lo); A tile [128 rows][16 k] stride 20; B tile same.
// word8-index = r*20 + k  ->  mod 16 = 4r + k  -> conflict-free LDS.64 frag loads.
#define TILE_F2   2560              // 128*20
#define STAGE_F2  (2*TILE_F2)       // A + B
#define SMEM_BYTES (2*STAGE_F2*8)   // double buffered = 81920

// compute one k16 chunk: 2 k8-steps, 48 mma each (4m x 4n x 3 split terms)
__device__ __forceinline__ void tile_compute(const float2* As, const float2* Bs,
                                             float c[4][4][4], int lane, int wm, int wn)
{
    const int grp = lane >> 2, tg = lane & 3;
    #pragma unroll
    for (int s = 0; s < 2; ++s) {
        const int kb = s*8;
        uint32_t ah[4][4], al[4][4], bh[4][2], bl[4][2];
        #pragma unroll
        for (int i = 0; i < 4; ++i) {
            int r0 = wm*64 + i*16 + grp;
            int kk = kb + tg;
            float2 p0 = As[r0*20 + kk];
            float2 p1 = As[(r0+8)*20 + kk];
            float2 p2 = As[r0*20 + kk + 4];
            float2 p3 = As[(r0+8)*20 + kk + 4];
            ah[i][0] = __float_as_uint(p0.x); ah[i][1] = __float_as_uint(p1.x);
            ah[i][2] = __float_as_uint(p2.x); ah[i][3] = __float_as_uint(p3.x);
            al[i][0] = __float_as_uint(p0.y); al[i][1] = __float_as_uint(p1.y);
            al[i][2] = __float_as_uint(p2.y); al[i][3] = __float_as_uint(p3.y);
        }
        #pragma unroll
        for (int j = 0; j < 4; ++j) {
            int n0 = wn*32 + j*8 + grp;
            int kk = kb + tg;
            float2 q0 = Bs[n0*20 + kk];
            float2 q1 = Bs[n0*20 + kk + 4];
            bh[j][0] = __float_as_uint(q0.x); bh[j][1] = __float_as_uint(q1.x);
            bl[j][0] = __float_as_uint(q0.y); bl[j][1] = __float_as_uint(q1.y);
        }
        #pragma unroll
        for (int i = 0; i < 4; ++i)
            #pragma unroll
            for (int j = 0; j < 4; ++j) {
                mma8(c[i][j], ah[i], bh[j]);
                mma8(c[i][j], ah[i], bl[j]);
                mma8(c[i][j], al[i], bh[j]);
            }
    }
}

// ----------------- tensor-core implicit-GEMM conv -----------------
// tile: 128(cout) x 128(pixels) x 16(k); grid (NPIX/128, ceil(COUTG/128), GROUPS)
template<int CING, int HH, int WW, int COUTG, int COUTT, int KH, int KW,
         int STR, int PAD, int OH, int OW, int GROUPS>
__global__ __launch_bounds__(256)
void conv_tc(const float* __restrict__ x, const float* __restrict__ w,
             const float* __restrict__ bias, float* __restrict__ out, float scale)
{
    constexpr int K    = CING*KH*KW;
    constexpr int CINT = CING*GROUPS;
    constexpr int OHW  = OH*OW;
    constexpr int NCH  = (K + 15)/16;

    extern __shared__ float2 smem2[];

    const int g    = blockIdx.z;
    const int pix0 = blockIdx.x * 128;
    const int m0   = blockIdx.y * 128;
    const int t    = threadIdx.x;
    const int lane = t & 31, warp = t >> 5;
    const int wm   = warp & 1, wn = warp >> 1;
    const int krel = t & 15;
    const int rbase = t >> 4;    // 0..15

    // precompute pixel decode for the 8 B-rows this thread loads
    int ihb[8], iwb[8], xb[8];
    #pragma unroll
    for (int p = 0; p < 8; ++p) {
        int pix = pix0 + rbase + p*16;
        int n   = pix / OHW; int rem = pix - n*OHW;
        int oh  = rem / OW;  int ow  = rem - oh*OW;
        ihb[p] = oh*STR - PAD; iwb[p] = ow*STR - PAD;
        xb[p]  = (n*CINT + g*CING)*HH*WW;
    }
    const float* wbase = w + (size_t)(g*COUTG)*K;

    float va[8], vb[8];
    auto gload = [&](int kb) {
        int kg = kb + krel;
        bool kv = kg < K;
        int kc = kv ? kg : 0;
        int ic = kc / (KH*KW);
        int r2 = kc - ic*(KH*KW);
        int kh = r2 / KW, kw = r2 - kh*KW;
        #pragma unroll
        for (int p = 0; p < 8; ++p) {
            int m = m0 + rbase + p*16;
            va[p] = (kv && m < COUTG) ? wbase[(size_t)m*K + kg] : 0.f;
            int ih = ihb[p] + kh, iw = iwb[p] + kw;
            float v = 0.f;
            if (kv && (unsigned)ih < (unsigned)HH && (unsigned)iw < (unsigned)WW)
                v = x[xb[p] + ic*HH*WW + ih*WW + iw] * scale;
            vb[p] = v;
        }
    };
    auto store = [&](int buf) {
        float2* As = smem2 + buf*STAGE_F2;
        float2* Bs = As + TILE_F2;
        #pragma unroll
        for (int p = 0; p < 8; ++p) {
            As[(rbase + p*16)*20 + krel] = split_tf32(va[p]);
            Bs[(rbase + p*16)*20 + krel] = split_tf32(vb[p]);
        }
    };

    float c[4][4][4];
    #pragma unroll
    for (int i = 0; i < 4; ++i)
        #pragma unroll
        for (int j = 0; j < 4; ++j)
            #pragma unroll
            for (int e = 0; e < 4; ++e) c[i][j][e] = 0.f;

    gload(0); store(0);
    __syncthreads();
    for (int ch = 0; ch < NCH; ++ch) {
        int buf = ch & 1;
        if (ch + 1 < NCH) gload((ch+1)*16);
        tile_compute(smem2 + buf*STAGE_F2, smem2 + buf*STAGE_F2 + TILE_F2, c, lane, wm, wn);
        __syncthreads();
        if (ch + 1 < NCH) { store(buf ^ 1); }
        __syncthreads();
    }

    // epilogue: bias + relu, scatter to NCHW
    const int grp = lane >> 2, tg = lane & 3;
    #pragma unroll
    for (int i = 0; i < 4; ++i) {
        #pragma unroll
        for (int e2 = 0; e2 < 2; ++e2) {
            int m = m0 + wm*64 + i*16 + grp + e2*8;
            if (m >= COUTG) continue;
            float bv = bias[g*COUTG + m];
            size_t obase = (size_t)(g*COUTG + m)*OHW;
            #pragma unroll
            for (int j = 0; j < 4; ++j) {
                #pragma unroll
                for (int e1 = 0; e1 < 2; ++e1) {
                    int pix = pix0 + wn*32 + j*8 + tg*2 + e1;
                    int n   = pix / OHW; int rem = pix - n*OHW;
                    float v = fmaxf(c[i][j][e2*2 + e1] + bv, 0.f);
                    out[(size_t)n*COUTT*OHW + obase + rem] = v;
                }
            }
        }
    }
}

// ----------------- tensor-core FC GEMM (nt), split-K -----------------
// C_part[z][128, Ntot] = A[128, kchunk] . B[Ntot, kchunk]^T ; grid (Ntot/128, 1, S)
__global__ __launch_bounds__(256)
void fc_tc(const float* __restrict__ A, const float* __restrict__ B,
           float* __restrict__ part, int Ntot, int K, int Kc)
{
    extern __shared__ float2 smem2[];
    const int n0g  = blockIdx.x * 128;
    const int z    = blockIdx.z;
    const int kb0  = z * Kc;
    const int t    = threadIdx.x;
    const int lane = t & 31, warp = t >> 5;
    const int wm   = warp & 1, wn = warp >> 1;
    const int krel = t & 15;
    const int rbase = t >> 4;
    const int NCH  = Kc / 16;

    float va[8], vb[8];
    auto gload = [&](int kb) {
        int kg = kb0 + kb + krel;
        #pragma unroll
        for (int p = 0; p < 8; ++p) {
            int r = rbase + p*16;
            va[p] = A[(size_t)r*K + kg];
            vb[p] = B[(size_t)(n0g + r)*K + kg];
        }
    };
    auto store = [&](int buf) {
        float2* As = smem2 + buf*STAGE_F2;
        float2* Bs = As + TILE_F2;
        #pragma unroll
        for (int p = 0; p < 8; ++p) {
            As[(rbase + p*16)*20 + krel] = split_tf32(va[p]);
            Bs[(rbase + p*16)*20 + krel] = split_tf32(vb[p]);
        }
    };

    float c[4][4][4];
    #pragma unroll
    for (int i = 0; i < 4; ++i)
        #pragma unroll
        for (int j = 0; j < 4; ++j)
            #pragma unroll
            for (int e = 0; e < 4; ++e) c[i][j][e] = 0.f;

    gload(0); store(0);
    __syncthreads();
    for (int ch = 0; ch < NCH; ++ch) {
        int buf = ch & 1;
        if (ch + 1 < NCH) gload((ch+1)*16);
        tile_compute(smem2 + buf*STAGE_F2, smem2 + buf*STAGE_F2 + TILE_F2, c, lane, wm, wn);
        __syncthreads();
        if (ch + 1 < NCH) { store(buf ^ 1); }
        __syncthreads();
    }

    const int grp = lane >> 2, tg = lane & 3;
    #pragma unroll
    for (int i = 0; i < 4; ++i)
        #pragma unroll
        for (int e2 = 0; e2 < 2; ++e2) {
            int m = wm*64 + i*16 + grp + e2*8;
            #pragma unroll
            for (int j = 0; j < 4; ++j) {
                int n = n0g + wn*32 + j*8 + tg*2;
                float2 v; v.x = c[i][j][e2*2]; v.y = c[i][j][e2*2 + 1];
                *(float2*)&part[((size_t)z*128 + m)*Ntot + n] = v;
            }
        }
}

// ----------------- split-K reduce + bias/relu/mask epilogue (N=4096) -----------------
__global__ void reduce_k(const float* __restrict__ part, const float* __restrict__ bias,
                         const float* __restrict__ maskref, float* __restrict__ C,
                         int MN, int S, int doRelu)
{
    int i = blockIdx.x*256 + threadIdx.x;
    if (i >= MN) return;
    float s = 0.f;
    for (int z = 0; z < S; ++z) s += part[(size_t)z*MN + i];
    if (bias) s += bias[i & 4095];
    if (doRelu) s = fmaxf(s, 0.f);
    if (maskref) s = (maskref[i] > 0.f) ? s : 0.f;
    C[i] = s;
}

// ----------------- 32x32 tiled transpose (w7 -> w7T) -----------------
__global__ void transpose_k(const float* __restrict__ in, float* __restrict__ outp)
{
    __shared__ float tile[32][33];
    int bx = blockIdx.x*32, by = blockIdx.y*32;
    int tx = threadIdx.x, ty = threadIdx.y;
    #pragma unroll
    for (int j = 0; j < 32; j += 8)
        tile[ty + j][tx] = in[(size_t)(by + ty + j)*4096 + bx + tx];
    __syncthreads();
    #pragma unroll
    for (int j = 0; j < 32; j += 8)
        outp[(size_t)(bx + ty + j)*4096 + by + tx] = tile[tx][ty + j];
}

// ----------------- maxpool 3x3 stride 2 -----------------
template<int C, int HI, int HO>
__global__ void pool_kernel(const float* __restrict__ in, float* __restrict__ out)
{
    constexpr int TOT = BATCH*C*HO*HO;
    int idx = blockIdx.x*256 + threadIdx.x;
    if (idx >= TOT) return;
    int ox = idx % HO;
    int tq = idx / HO;
    int oy = tq % HO;
    int nc = tq / HO;
    const float* p = in + (nc*HI + oy*2)*HI + ox*2;
    float m = -3.4e38f;
    #pragma unroll
    for (int a = 0; a < 3; ++a)
        #pragma unroll
        for (int b = 0; b < 3; ++b)
            m = fmaxf(m, p[a*HI + b]);
    out[idx] = m;
}

// ----------------- LRN -----------------
template<int C, int HW>
__global__ void lrn_kernel(const float* __restrict__ in, float* __restrict__ out)
{
    constexpr int TOT = BATCH*C*HW;
    int idx = blockIdx.x*256 + threadIdx.x;
    if (idx >= TOT) return;
    int s = idx % HW;
    int c = (idx / HW) % C;
    int n = idx / (HW*C);
    const float* base = in + n*C*HW + s;
    float sum = 0.f;
    #pragma unroll
    for (int d = -2; d <= 2; ++d) {
        int cc = c + d;
        if (cc >= 0 && cc < C) {
            float v = base[cc*HW];
            sum = fmaf(v, v, sum);
        }
    }
    float r = rsqrtf(fmaf(2e-5f, sum, 1.0f));
    out[idx] = in[idx] * r * sqrtf(r);
}

// ----------------- fold w6 over channels -----------------
__global__ void w6fold_k(const float* __restrict__ w6, float* __restrict__ w6r)
{
    int i = blockIdx.x*256 + threadIdx.x;
    if (i >= 4096*36) return;
    int j = i / 36, s = i - j*36;
    const float* p = w6 + (size_t)j*9216 + s;
    float acc = 0.f;
    for (int c = 0; c < 256; ++c) acc += p[c*36];
    w6r[i] = acc * (1.f/256.f);
}

// ----------------- sm[n,s] = g1[n,:] . w6r[:,s] -----------------
__global__ void smgemm_k(const float* __restrict__ g1, const float* __restrict__ w6r,
                         float* __restrict__ sm)
{
    __shared__ float gs[4096];
    int n = blockIdx.x, t = threadIdx.x;
    for (int k = t; k < 4096; k += 256) gs[k] = g1[n*4096 + k];
    __syncthreads();
    int warp = t >> 5, lane = t & 31;
    for (int s = warp; s < 36; s += 8) {
        float acc = 0.f;
        for (int k = lane; k < 4096; k += 32) acc += gs[k] * w6r[k*36 + s];
        #pragma unroll
        for (int o = 16; o; o >>= 1) acc += __shfl_xor_sync(0xffffffffu, acc, o);
        if (lane == 0) sm[n*36 + s] = acc;
    }
}

// ----------------- classifier dot -----------------
__global__ void cls_kernel(const float* __restrict__ h, const float* __restrict__ wc,
                           const float* __restrict__ bc, float* __restrict__ out)
{
    int n = blockIdx.x;
    int warp = threadIdx.x >> 5, lane = threadIdx.x & 31;
    int c = blockIdx.y*8 + warp;
    if (c >= 100) return;
    const float4* hp = (const float4*)(h + n*4096);
    const float4* wp = (const float4*)(wc + c*4096);
    float s = 0.f;
    for (int k = lane; k < 1024; k += 32) {
        float4 a = hp[k], b = wp[k];
        s += a.x*b.x + a.y*b.y + a.z*b.z + a.w*b.w;
    }
    #pragma unroll
    for (int o = 16; o; o >>= 1) s += __shfl_xor_sync(0xffffffffu, s, o);
    if (lane == 0) out[n*100 + c] = s + bc[c];
}

// ----------------- softmax probability at gt -----------------
__global__ void softgt_kernel(const float* __restrict__ logits, const int* __restrict__ gt,
                              float* __restrict__ cls)
{
    int n = blockIdx.x;
    int lane = threadIdx.x;
    float m = -3.4e38f;
    for (int c = lane; c < 100; c += 32) m = fmaxf(m, logits[n*100 + c]);
    #pragma unroll
    for (int o = 16; o; o >>= 1) m = fmaxf(m, __shfl_xor_sync(0xffffffffu, m, o));
    float s = 0.f;
    for (int c = lane; c < 100; c += 32) s += expf(logits[n*100 + c] - m);
    #pragma unroll
    for (int o = 16; o; o >>= 1) s += __shfl_xor_sync(0xffffffffu, s, o);
    if (lane == 0) cls[n] = expf(logits[n*100 + gt[n]] - m) / s;
}

// ----------------- g2 = relu'(h2) * wc[gt] -----------------
__global__ void g2m_kernel(const float* __restrict__ h2, const float* __restrict__ wc,
                           const int* __restrict__ gt, float* __restrict__ g2)
{
    int idx = blockIdx.x*256 + threadIdx.x;
    if (idx >= BATCH*4096) return;
    int n = idx >> 12, j = idx & 4095;
    g2[idx] = (h2[idx] > 0.f) ? wc[gt[n]*4096 + j] : 0.f;
}

// ----------------- per-sample RSC spatial mask -----------------
__global__ void mask_kernel(const float* __restrict__ sm, const float* __restrict__ u,
                            const int* __restrict__ flag, float* __restrict__ mask)
{
    int n = threadIdx.x;
    if (n >= BATCH) return;
    if (*flag == 0) {
        for (int s = 0; s < 36; ++s) mask[n*36 + s] = 1.f;
        return;
    }
    float v[36], tmp[36], sc[36], mk[36];
    for (int s = 0; s < 36; ++s) { v[s] = sm[n*36 + s]; tmp[s] = v[s]; mk[s] = 1.f; }
    float th = 0.f;
    for (int it = 0; it < 13; ++it) {
        int bi = 0; float bv = tmp[0];
        for (int s = 1; s < 36; ++s) if (tmp[s] > bv) { bv = tmp[s]; bi = s; }
        th = bv; tmp[bi] = -3.4e38f;
    }
    for (int s = 0; s < 36; ++s) sc[s] = (v[s] >= th) ? u[n*36 + s] : -1.f;
    for (int it = 0; it < 12; ++it) {
        int bi = 0; float bv = sc[0];
        for (int s = 1; s < 36; ++s) if (sc[s] > bv) { bv = sc[s]; bi = s; }
        mk[bi] = 0.f; sc[bi] = -2.f;
    }
    for (int s = 0; s < 36; ++s) mask[n*36 + s] = mk[s];
}

// ----------------- apply spatial mask -----------------
__global__ void applymask_kernel(const float* __restrict__ f, const float* __restrict__ mask,
                                 float* __restrict__ o)
{
    int i = blockIdx.x*256 + threadIdx.x;
    if (i >= BATCH*9216) return;
    int n = i / 9216;
    int s = i % 36;
    o[i] = f[i] * mask[n*36 + s];
}

// ----------------- keep decision + per-row output select -----------------
__global__ void keepsel_kernel(const float* __restrict__ clsb, const float* __restrict__ clsa,
                               const float* __restrict__ out0, const float* __restrict__ outb,
                               float* __restrict__ out)
{
    __shared__ float cv[BATCH];
    __shared__ float thf;
    int n = threadIdx.x;
    cv[n] = fmaxf(clsb[n] - clsa[n] - 1e-4f, 0.f);
    __syncthreads();
    if (n == 0) {
        float tmp[BATCH];
        for (int i = 0; i < BATCH; ++i) tmp[i] = cv[i];
        float bv = 0.f;
        for (int it = 0; it < 44; ++it) {
            int bi = 0; bv = tmp[0];
            for (int i = 1; i < BATCH; ++i) if (tmp[i] > bv) { bv = tmp[i]; bi = i; }
            tmp[bi] = -3.4e38f;
        }
        thf = bv;
    }
    __syncthreads();
    bool keep = !(cv[n] > thf);
    const float* src = keep ? out0 : outb;
    for (int c = 0; c < 100; ++c) out[n*100 + c] = src[n*100 + c];
}

// ----------------- launch -----------------
static float* sym(const void* symbol)
{
    void* p = nullptr;
    cudaGetSymbolAddress(&p, symbol);
    return (float*)p;
}

extern "C" void kernel_launch(void* const* d_in, const int* in_sizes, int n_in,
                              void* d_out, int out_size)
{
    const float* x    = (const float*)d_in[0];
    const int*   gt   = (const int*)  d_in[1];
    const float* u    = (const float*)d_in[2];
    const int*   flag = (const int*)  d_in[3];
    const float* w1 = (const float*)d_in[4];  const float* b1 = (const float*)d_in[5];
    const float* w2 = (const float*)d_in[6];  const float* b2 = (const float*)d_in[7];
    const float* w3 = (const float*)d_in[8];  const float* b3 = (const float*)d_in[9];
    const float* w4 = (const float*)d_in[10]; const float* b4 = (const float*)d_in[11];
    const float* w5 = (const float*)d_in[12]; const float* b5 = (const float*)d_in[13];
    const float* w6 = (const float*)d_in[14]; const float* b6 = (const float*)d_in[15];
    const float* w7 = (const float*)d_in[16]; const float* b7 = (const float*)d_in[17];
    const float* wc = (const float*)d_in[18]; const float* bc = (const float*)d_in[19];
    float* out = (float*)d_out;

    float* c1   = sym(d_c1);   float* p1   = sym(d_p1);   float* l1   = sym(d_l1);
    float* c2   = sym(d_c2);   float* p2   = sym(d_p2);   float* l2   = sym(d_l2);
    float* c3   = sym(d_c3);   float* c4   = sym(d_c4);   float* c5   = sym(d_c5);
    float* feat = sym(d_feat);
    float* h1   = sym(d_h1);   float* h2   = sym(d_h2);   float* out0 = sym(d_out0);
    float* g2   = sym(d_g2);   float* g1   = sym(d_g1);
    float* smv  = sym(d_sm);   float* mask = sym(d_mask);
    float* featm= sym(d_featm);float* h1b  = sym(d_h1b);  float* h2b  = sym(d_h2b);
    float* outb = sym(d_outb); float* clsb = sym(d_clsb); float* clsa = sym(d_clsa);
    float* w6r  = sym(d_w6r);  float* w7t  = sym(d_w7t);  float* part = sym(d_part);

    const int MN = BATCH*4096;

    // opt-in to >48KB dynamic smem for all tensor kernels
    cudaFuncSetAttribute(conv_tc<3,227,227,96,96,11,11,4,0,55,55,1>,  cudaFuncAttributeMaxDynamicSharedMemorySize, SMEM_BYTES);
    cudaFuncSetAttribute(conv_tc<48,27,27,128,256,5,5,1,2,27,27,2>,   cudaFuncAttributeMaxDynamicSharedMemorySize, SMEM_BYTES);
    cudaFuncSetAttribute(conv_tc<256,13,13,384,384,3,3,1,1,13,13,1>,  cudaFuncAttributeMaxDynamicSharedMemorySize, SMEM_BYTES);
    cudaFuncSetAttribute(conv_tc<192,13,13,192,384,3,3,1,1,13,13,2>,  cudaFuncAttributeMaxDynamicSharedMemorySize, SMEM_BYTES);
    cudaFuncSetAttribute(conv_tc<192,13,13,128,256,3,3,1,1,13,13,2>,  cudaFuncAttributeMaxDynamicSharedMemorySize, SMEM_BYTES);
    cudaFuncSetAttribute(fc_tc, cudaFuncAttributeMaxDynamicSharedMemorySize, SMEM_BYTES);

    // ---- prep: folded w6 (gradient shortcut) + transposed w7 (nt-form grad GEMM) ----
    w6fold_k<<<(4096*36 + 255)/256, 256>>>(w6, w6r);
    transpose_k<<<dim3(128,128), dim3(32,8)>>>(w7, w7t);

    // ---- feature extractor (tensor-core implicit GEMM) ----
    conv_tc<3,227,227,96,96,11,11,4,0,55,55,1><<<dim3(3025,1,1),256,SMEM_BYTES>>>(x, w1, b1, c1, 57.6f);
    pool_kernel<96,55,27><<<34992,256>>>(c1, p1);
    lrn_kernel<96,729><<<34992,256>>>(p1, l1);
    conv_tc<48,27,27,128,256,5,5,1,2,27,27,2><<<dim3(729,1,2),256,SMEM_BYTES>>>(l1, w2, b2, c2, 1.f);
    pool_kernel<256,27,13><<<21632,256>>>(c2, p2);
    lrn_kernel<256,169><<<21632,256>>>(p2, l2);
    conv_tc<256,13,13,384,384,3,3,1,1,13,13,1><<<dim3(169,3,1),256,SMEM_BYTES>>>(l2, w3, b3, c3, 1.f);
    conv_tc<192,13,13,192,384,3,3,1,1,13,13,2><<<dim3(169,2,2),256,SMEM_BYTES>>>(c3, w4, b4, c4, 1.f);
    conv_tc<192,13,13,128,256,3,3,1,1,13,13,2><<<dim3(169,1,2),256,SMEM_BYTES>>>(c4, w5, b5, c5, 1.f);
    pool_kernel<256,13,6><<<4608,256>>>(c5, feat);

    // ---- head #1 (unmasked) ----
    fc_tc<<<dim3(32,1,4),256,SMEM_BYTES>>>(feat, w6, part, 4096, 9216, 2304);
    reduce_k<<<2048,256>>>(part, b6, nullptr, h1, MN, 4, 1);
    fc_tc<<<dim3(32,1,4),256,SMEM_BYTES>>>(h1, w7, part, 4096, 4096, 1024);
    reduce_k<<<2048,256>>>(part, b7, nullptr, h2, MN, 4, 1);
    cls_kernel<<<dim3(128,13),256>>>(h2, wc, bc, out0);
    softgt_kernel<<<128,32>>>(out0, gt, clsb);

    // ---- analytic gradient of out[n,gt] wrt features (folded to spatial mean) ----
    g2m_kernel<<<2048,256>>>(h2, wc, gt, g2);
    fc_tc<<<dim3(32,1,4),256,SMEM_BYTES>>>(g2, w7t, part, 4096, 4096, 1024);
    reduce_k<<<2048,256>>>(part, nullptr, h1, g1, MN, 4, 0);
    smgemm_k<<<128,256>>>(g1, w6r, smv);

    // ---- RSC spatial mask ----
    mask_kernel<<<1,128>>>(smv, u, flag, mask);
    applymask_kernel<<<4608,256>>>(feat, mask, featm);

    // ---- head #2 (masked) ----
    fc_tc<<<dim3(32,1,4),256,SMEM_BYTES>>>(featm, w6, part, 4096, 9216, 2304);
    reduce_k<<<2048,256>>>(part, b6, nullptr, h1b, MN, 4, 1);
    fc_tc<<<dim3(32,1,4),256,SMEM_BYTES>>>(h1b, w7, part, 4096, 4096, 1024);
    reduce_k<<<2048,256>>>(part, b7, nullptr, h2b, MN, 4, 1);
    cls_kernel<<<dim3(128,13),256>>>(h2b, wc, bc, outb);
    softgt_kernel<<<128,32>>>(outb, gt, clsa);

    // ---- keep decision + final per-row select ----
    keepsel_kernel<<<1,128>>>(clsb, clsa, out0, outb, out);

    (void)in_sizes; (void)n_in; (void)out_size;
}

// round 5
// speedup vs baseline: 1.1347x; 1.1347x over previous
#include <cuda_runtime.h>
#include <math.h>
#include <stdint.h>

#define BATCH 128

// ----------------- scratch buffers -----------------
__device__ float d_c1[BATCH*96*55*55];
__device__ float d_l1[BATCH*96*27*27];
__device__ float d_c2[BATCH*256*27*27];
__device__ float d_l2[BATCH*256*13*13];
__device__ float d_c3[BATCH*384*13*13];
__device__ float d_c4[BATCH*384*13*13];
__device__ float d_c5[BATCH*256*13*13];
__device__ float d_feat[BATCH*9216];
__device__ float d_h1[BATCH*4096];
__device__ float d_h2[BATCH*4096];
__device__ float d_out0[BATCH*100];
__device__ float d_g2[BATCH*4096];
__device__ float d_g1[BATCH*4096];
__device__ float d_sm[BATCH*36];
__device__ float d_mask[BATCH*36];
__device__ float d_featm[BATCH*9216];
__device__ float d_h1b[BATCH*4096];
__device__ float d_h2b[BATCH*4096];
__device__ float d_outb[BATCH*100];
__device__ float d_clsb[BATCH];
__device__ float d_clsa[BATCH];
__device__ float d_w6r[4096*36];
__device__ float d_w7t[4096*4096];
__device__ float d_part[8*BATCH*4096];

// ----------------- f32x2 helpers -----------------
__device__ __forceinline__ void fma2(unsigned long long& d, unsigned long long a, unsigned long long b) {
    asm("fma.rn.f32x2 %0, %1, %2, %0;" : "+l"(d) : "l"(a), "l"(b));
}
__device__ __forceinline__ float2 unpack2(unsigned long long v) {
    unsigned lo, hi;
    asm("mov.b64 {%0, %1}, %2;" : "=r"(lo), "=r"(hi) : "l"(v));
    float2 f; f.x = __uint_as_float(lo); f.y = __uint_as_float(hi); return f;
}

#define BSTR 258          // dup-B row stride (floats): 2*128+2 -> conflict-free
// A row stride = MT+2

// ----------------- implicit-GEMM conv, f32x2 dup-B microtile -----------------
// Tile MT(cout) x 128(pixels) x 16(K); 256 threads; micro (MT/32 row-pairs) x 8 cols.
template<int CING, int HH, int WW, int COUTG, int COUTT, int KH, int KW,
         int STR, int PAD, int OH, int OW, int GROUPS, int MT>
__global__ __launch_bounds__(256, 2)
void conv_f2b(const float* __restrict__ x, const float* __restrict__ w,
              const float* __restrict__ bias, float* __restrict__ out, float scale)
{
    constexpr int K    = CING*KH*KW;
    constexpr int CINT = CING*GROUPS;
    constexpr int OHW  = OH*OW;
    constexpr int NCH  = (K + 15)/16;
    constexpr int MI   = MT/16;     // A rows loaded per thread
    constexpr int MI2  = MT/32;     // acc row-pairs per thread
    constexpr int ASTR = MT + 2;

    extern __shared__ __align__(16) float smf[];
    float* A0 = smf;                    // 2 stages * 16 * ASTR
    float* B0 = smf + 2*16*ASTR;        // 2 stages * 16 * BSTR

    const int g    = blockIdx.z;
    const int pix0 = blockIdx.x * 128;
    const int m0   = blockIdx.y * MT;
    const int t    = threadIdx.x;
    const int tx   = t & 15, ty = t >> 4;
    const int lk   = t & 15, lr = t >> 4;

    // per-pixel decode: base address + validity bitmasks
    int pbase[8], vm[8];
    #pragma unroll
    for (int p = 0; p < 8; ++p) {
        int pix = pix0 + lr + p*16;
        int n   = pix / OHW; int rem = pix - n*OHW;
        int oh  = rem / OW;  int ow  = rem - oh*OW;
        int ihb = oh*STR - PAD, iwb = ow*STR - PAD;
        pbase[p] = (n*CINT + g*CING)*HH*WW + ihb*WW + iwb;
        int m1 = 0, m2 = 0;
        #pragma unroll
        for (int kh = 0; kh < KH; ++kh) if ((unsigned)(ihb + kh) < (unsigned)HH) m1 |= 1 << kh;
        #pragma unroll
        for (int kw = 0; kw < KW; ++kw) if ((unsigned)(iwb + kw) < (unsigned)WW) m2 |= 1 << kw;
        vm[p] = m1 | (m2 << 16);
    }
    const float* wbase = w + (size_t)(g*COUTG)*K;

    float ra[MI], rb[8];
    auto loadA = [&](int k0) {
        int kg = k0 + lk; bool kv = kg < K;
        #pragma unroll
        for (int p = 0; p < MI; ++p)
            ra[p] = kv ? wbase[(size_t)(m0 + lr + p*16)*K + kg] : 0.f;
    };
    auto loadB = [&](int k0) {
        int kg = k0 + lk; bool kv = kg < K;
        int kc = kv ? kg : 0;
        int ic = kc / (KH*KW);
        int r2 = kc - ic*(KH*KW);
        int kh = r2 / KW, kw = r2 - kh*KW;
        int koff = ic*HH*WW + kh*WW + kw;
        #pragma unroll
        for (int p = 0; p < 8; ++p) {
            bool ok;
            if (PAD == 0) ok = kv;
            else ok = kv && ((vm[p] >> kh) & 1) && ((vm[p] >> (16 + kw)) & 1);
            rb[p] = ok ? x[pbase[p] + koff] * scale : 0.f;
        }
    };
    auto store = [&](int buf) {
        float* As = A0 + buf*16*ASTR;
        float* Bs = B0 + buf*16*BSTR;
        #pragma unroll
        for (int p = 0; p < MI; ++p)
            As[lk*ASTR + lr + p*16] = ra[p];
        #pragma unroll
        for (int p = 0; p < 8; ++p) {
            float2 v; v.x = rb[p]; v.y = rb[p];
            *(float2*)&Bs[lk*BSTR + 2*(lr + p*16)] = v;
        }
    };

    unsigned long long acc[MI2][8];
    #pragma unroll
    for (int i = 0; i < MI2; ++i)
        #pragma unroll
        for (int j = 0; j < 8; ++j) acc[i][j] = 0ull;

    loadA(0); loadB(0); store(0);
    __syncthreads();
    for (int ch = 0; ch < NCH; ++ch) {
        int buf = ch & 1;
        if (ch + 1 < NCH) { loadA((ch+1)*16); loadB((ch+1)*16); }
        const float* Ab = A0 + buf*16*ASTR;
        const float* Bb = B0 + buf*16*BSTR;
        #pragma unroll
        for (int kk = 0; kk < 16; ++kk) {
            unsigned long long a2[MI2], b2[8];
            #pragma unroll
            for (int i = 0; i < MI2; ++i)
                a2[i] = *(const unsigned long long*)&Ab[kk*ASTR + 2*ty + 32*i];
            #pragma unroll
            for (int j = 0; j < 8; ++j)
                b2[j] = *(const unsigned long long*)&Bb[kk*BSTR + 2*tx + 32*j];
            #pragma unroll
            for (int i = 0; i < MI2; ++i)
                #pragma unroll
                for (int j = 0; j < 8; ++j) fma2(acc[i][j], a2[i], b2[j]);
        }
        if (ch + 1 < NCH) store(buf ^ 1);
        __syncthreads();
    }

    // epilogue: bias + relu, scatter NCHW (lanes write consecutive pixels -> coalesced)
    #pragma unroll
    for (int i = 0; i < MI2; ++i) {
        int m = m0 + 2*ty + 32*i;
        float bv0 = bias[g*COUTG + m];
        float bv1 = bias[g*COUTG + m + 1];
        size_t ob0 = (size_t)(g*COUTG + m)*OHW;
        size_t ob1 = ob0 + OHW;
        #pragma unroll
        for (int j = 0; j < 8; ++j) {
            int pix = pix0 + tx + 16*j;
            int n   = pix / OHW; int rem = pix - n*OHW;
            size_t nb = (size_t)n*COUTT*OHW;
            float2 v = unpack2(acc[i][j]);
            out[nb + ob0 + rem] = fmaxf(v.x + bv0, 0.f);
            out[nb + ob1 + rem] = fmaxf(v.y + bv1, 0.f);
        }
    }
}
#define SM_CONV(MT) ((2*16*((MT)+2) + 2*16*BSTR)*4)

// ----------------- FC GEMM nt, f32x2 dup-B, 128x128x16, split-K -----------------
// part[z][128, Ntot] = A[128, kchunk] . B[Ntot, kchunk]^T ; grid (Ntot/128, 1, S)
__global__ __launch_bounds__(256, 2)
void fc_f2b(const float* __restrict__ A, const float* __restrict__ B,
            float* __restrict__ part, int Ntot, int K, int Kc)
{
    constexpr int ASTR = 130;
    extern __shared__ __align__(16) float smf[];
    float* A0 = smf;
    float* B0 = smf + 2*16*ASTR;

    const int n0g = blockIdx.x * 128;
    const int z   = blockIdx.z;
    const int kb0 = z * Kc;
    const int t   = threadIdx.x;
    const int tx  = t & 15, ty = t >> 4;
    const int lk  = t & 15, lr = t >> 4;
    const int NCH = Kc >> 4;

    float ra[8], rb[8];
    auto loadAB = [&](int k0) {
        int kg = kb0 + k0 + lk;
        #pragma unroll
        for (int p = 0; p < 8; ++p) {
            int r = lr + p*16;
            ra[p] = A[(size_t)r*K + kg];
            rb[p] = B[(size_t)(n0g + r)*K + kg];
        }
    };
    auto store = [&](int buf) {
        float* As = A0 + buf*16*ASTR;
        float* Bs = B0 + buf*16*BSTR;
        #pragma unroll
        for (int p = 0; p < 8; ++p)
            As[lk*ASTR + lr + p*16] = ra[p];
        #pragma unroll
        for (int p = 0; p < 8; ++p) {
            float2 v; v.x = rb[p]; v.y = rb[p];
            *(float2*)&Bs[lk*BSTR + 2*(lr + p*16)] = v;
        }
    };

    unsigned long long acc[4][8];
    #pragma unroll
    for (int i = 0; i < 4; ++i)
        #pragma unroll
        for (int j = 0; j < 8; ++j) acc[i][j] = 0ull;

    loadAB(0); store(0);
    __syncthreads();
    for (int ch = 0; ch < NCH; ++ch) {
        int buf = ch & 1;
        if (ch + 1 < NCH) loadAB((ch+1)*16);
        const float* Ab = A0 + buf*16*ASTR;
        const float* Bb = B0 + buf*16*BSTR;
        #pragma unroll
        for (int kk = 0; kk < 16; ++kk) {
            unsigned long long a2[4], b2[8];
            #pragma unroll
            for (int i = 0; i < 4; ++i)
                a2[i] = *(const unsigned long long*)&Ab[kk*ASTR + 2*ty + 32*i];
            #pragma unroll
            for (int j = 0; j < 8; ++j)
                b2[j] = *(const unsigned long long*)&Bb[kk*BSTR + 2*tx + 32*j];
            #pragma unroll
            for (int i = 0; i < 4; ++i)
                #pragma unroll
                for (int j = 0; j < 8; ++j) fma2(acc[i][j], a2[i], b2[j]);
        }
        if (ch + 1 < NCH) store(buf ^ 1);
        __syncthreads();
    }

    #pragma unroll
    for (int i = 0; i < 4; ++i) {
        int m = 2*ty + 32*i;
        #pragma unroll
        for (int j = 0; j < 8; ++j) {
            int n = n0g + tx + 16*j;
            float2 v = unpack2(acc[i][j]);
            part[((size_t)z*128 + m)*Ntot + n]     = v.x;
            part[((size_t)z*128 + m + 1)*Ntot + n] = v.y;
        }
    }
}
#define SM_FC ((2*16*130 + 2*16*BSTR)*4)

// ----------------- split-K reduce + bias/relu/mask epilogue (N=4096) -----------------
__global__ void reduce_k(const float* __restrict__ part, const float* __restrict__ bias,
                         const float* __restrict__ maskref, float* __restrict__ C,
                         int MN, int S, int doRelu)
{
    int i = blockIdx.x*256 + threadIdx.x;
    if (i >= MN) return;
    float s = 0.f;
    for (int z = 0; z < S; ++z) s += part[(size_t)z*MN + i];
    if (bias) s += bias[i & 4095];
    if (doRelu) s = fmaxf(s, 0.f);
    if (maskref) s = (maskref[i] > 0.f) ? s : 0.f;
    C[i] = s;
}

// ----------------- fused maxpool(3,2) + LRN(n=5) : block = (n, oy) -----------------
template<int C, int HI, int HO>
__global__ void poollrn_kernel(const float* __restrict__ in, float* __restrict__ out)
{
    __shared__ float pl[C*HO];
    int b = blockIdx.x;
    int n = b / HO, oy = b % HO;
    for (int idx = threadIdx.x; idx < C*HO; idx += 256) {
        int c = idx / HO, ox = idx - c*HO;
        const float* p = in + ((size_t)(n*C + c)*HI + oy*2)*HI + ox*2;
        float m = -3.4e38f;
        #pragma unroll
        for (int a = 0; a < 3; ++a)
            #pragma unroll
            for (int bq = 0; bq < 3; ++bq)
                m = fmaxf(m, p[a*HI + bq]);
        pl[idx] = m;
    }
    __syncthreads();
    for (int idx = threadIdx.x; idx < C*HO; idx += 256) {
        int c = idx / HO, ox = idx - c*HO;
        float sum = 0.f;
        #pragma unroll
        for (int d = -2; d <= 2; ++d) {
            int cc = c + d;
            if (cc >= 0 && cc < C) {
                float v = pl[cc*HO + ox];
                sum = fmaf(v, v, sum);
            }
        }
        float r = rsqrtf(fmaf(2e-5f, sum, 1.0f));
        out[((size_t)(n*C + c)*HO + oy)*HO + ox] = pl[idx] * r * sqrtf(r);
    }
}

// ----------------- maxpool 3x3 stride 2 (final 13->6) -----------------
template<int C, int HI, int HO>
__global__ void pool_kernel(const float* __restrict__ in, float* __restrict__ out)
{
    constexpr int TOT = BATCH*C*HO*HO;
    int idx = blockIdx.x*256 + threadIdx.x;
    if (idx >= TOT) return;
    int ox = idx % HO;
    int tq = idx / HO;
    int oy = tq % HO;
    int nc = tq / HO;
    const float* p = in + ((size_t)nc*HI + oy*2)*HI + ox*2;
    float m = -3.4e38f;
    #pragma unroll
    for (int a = 0; a < 3; ++a)
        #pragma unroll
        for (int b = 0; b < 3; ++b)
            m = fmaxf(m, p[a*HI + b]);
    out[idx] = m;
}

// ----------------- fold w6 over channels -----------------
__global__ void w6fold_k(const float* __restrict__ w6, float* __restrict__ w6r)
{
    int i = blockIdx.x*256 + threadIdx.x;
    if (i >= 4096*36) return;
    int j = i / 36, s = i - j*36;
    const float* p = w6 + (size_t)j*9216 + s;
    float acc = 0.f;
    for (int c = 0; c < 256; ++c) acc += p[c*36];
    w6r[i] = acc * (1.f/256.f);
}

// ----------------- 32x32 tiled transpose (w7 -> w7T) -----------------
__global__ void transpose_k(const float* __restrict__ in, float* __restrict__ outp)
{
    __shared__ float tile[32][33];
    int bx = blockIdx.x*32, by = blockIdx.y*32;
    int tx = threadIdx.x, ty = threadIdx.y;
    #pragma unroll
    for (int j = 0; j < 32; j += 8)
        tile[ty + j][tx] = in[(size_t)(by + ty + j)*4096 + bx + tx];
    __syncthreads();
    #pragma unroll
    for (int j = 0; j < 32; j += 8)
        outp[(size_t)(bx + ty + j)*4096 + by + tx] = tile[tx][ty + j];
}

// ----------------- sm[n,s] = g1[n,:] . w6r[:,s] -----------------
__global__ void smgemm_k(const float* __restrict__ g1, const float* __restrict__ w6r,
                         float* __restrict__ sm)
{
    __shared__ float gs[4096];
    int n = blockIdx.x, t = threadIdx.x;
    for (int k = t; k < 4096; k += 256) gs[k] = g1[n*4096 + k];
    __syncthreads();
    int warp = t >> 5, lane = t & 31;
    for (int s = warp; s < 36; s += 8) {
        float acc = 0.f;
        for (int k = lane; k < 4096; k += 32) acc += gs[k] * w6r[k*36 + s];
        #pragma unroll
        for (int o = 16; o; o >>= 1) acc += __shfl_xor_sync(0xffffffffu, acc, o);
        if (lane == 0) sm[n*36 + s] = acc;
    }
}

// ----------------- classifier dot -----------------
__global__ void cls_kernel(const float* __restrict__ h, const float* __restrict__ wc,
                           const float* __restrict__ bc, float* __restrict__ out)
{
    int n = blockIdx.x;
    int warp = threadIdx.x >> 5, lane = threadIdx.x & 31;
    int c = blockIdx.y*8 + warp;
    if (c >= 100) return;
    const float4* hp = (const float4*)(h + n*4096);
    const float4* wp = (const float4*)(wc + c*4096);
    float s = 0.f;
    for (int k = lane; k < 1024; k += 32) {
        float4 a = hp[k], b = wp[k];
        s += a.x*b.x + a.y*b.y + a.z*b.z + a.w*b.w;
    }
    #pragma unroll
    for (int o = 16; o; o >>= 1) s += __shfl_xor_sync(0xffffffffu, s, o);
    if (lane == 0) out[n*100 + c] = s + bc[c];
}

// ----------------- softmax probability at gt -----------------
__global__ void softgt_kernel(const float* __restrict__ logits, const int* __restrict__ gt,
                              float* __restrict__ cls)
{
    int n = blockIdx.x;
    int lane = threadIdx.x;
    float m = -3.4e38f;
    for (int c = lane; c < 100; c += 32) m = fmaxf(m, logits[n*100 + c]);
    #pragma unroll
    for (int o = 16; o; o >>= 1) m = fmaxf(m, __shfl_xor_sync(0xffffffffu, m, o));
    float s = 0.f;
    for (int c = lane; c < 100; c += 32) s += expf(logits[n*100 + c] - m);
    #pragma unroll
    for (int o = 16; o; o >>= 1) s += __shfl_xor_sync(0xffffffffu, s, o);
    if (lane == 0) cls[n] = expf(logits[n*100 + gt[n]] - m) / s;
}

// ----------------- g2 = relu'(h2) * wc[gt] -----------------
__global__ void g2m_kernel(const float* __restrict__ h2, const float* __restrict__ wc,
                           const int* __restrict__ gt, float* __restrict__ g2)
{
    int idx = blockIdx.x*256 + threadIdx.x;
    if (idx >= BATCH*4096) return;
    int n = idx >> 12, j = idx & 4095;
    g2[idx] = (h2[idx] > 0.f) ? wc[gt[n]*4096 + j] : 0.f;
}

// ----------------- per-sample RSC spatial mask -----------------
__global__ void mask_kernel(const float* __restrict__ sm, const float* __restrict__ u,
                            const int* __restrict__ flag, float* __restrict__ mask)
{
    int n = threadIdx.x;
    if (n >= BATCH) return;
    if (*flag == 0) {
        for (int s = 0; s < 36; ++s) mask[n*36 + s] = 1.f;
        return;
    }
    float v[36], tmp[36], sc[36], mk[36];
    for (int s = 0; s < 36; ++s) { v[s] = sm[n*36 + s]; tmp[s] = v[s]; mk[s] = 1.f; }
    float th = 0.f;
    for (int it = 0; it < 13; ++it) {
        int bi = 0; float bv = tmp[0];
        for (int s = 1; s < 36; ++s) if (tmp[s] > bv) { bv = tmp[s]; bi = s; }
        th = bv; tmp[bi] = -3.4e38f;
    }
    for (int s = 0; s < 36; ++s) sc[s] = (v[s] >= th) ? u[n*36 + s] : -1.f;
    for (int it = 0; it < 12; ++it) {
        int bi = 0; float bv = sc[0];
        for (int s = 1; s < 36; ++s) if (sc[s] > bv) { bv = sc[s]; bi = s; }
        mk[bi] = 0.f; sc[bi] = -2.f;
    }
    for (int s = 0; s < 36; ++s) mask[n*36 + s] = mk[s];
}

// ----------------- apply spatial mask -----------------
__global__ void applymask_kernel(const float* __restrict__ f, const float* __restrict__ mask,
                                 float* __restrict__ o)
{
    int i = blockIdx.x*256 + threadIdx.x;
    if (i >= BATCH*9216) return;
    int n = i / 9216;
    int s = i % 36;
    o[i] = f[i] * mask[n*36 + s];
}

// ----------------- keep decision + per-row output select -----------------
__global__ void keepsel_kernel(const float* __restrict__ clsb, const float* __restrict__ clsa,
                               const float* __restrict__ out0, const float* __restrict__ outb,
                               float* __restrict__ out)
{
    __shared__ float cv[BATCH];
    __shared__ float thf;
    int n = threadIdx.x;
    cv[n] = fmaxf(clsb[n] - clsa[n] - 1e-4f, 0.f);
    __syncthreads();
    if (n == 0) {
        float tmp[BATCH];
        for (int i = 0; i < BATCH; ++i) tmp[i] = cv[i];
        float bv = 0.f;
        for (int it = 0; it < 44; ++it) {
            int bi = 0; bv = tmp[0];
            for (int i = 1; i < BATCH; ++i) if (tmp[i] > bv) { bv = tmp[i]; bi = i; }
            tmp[bi] = -3.4e38f;
        }
        thf = bv;
    }
    __syncthreads();
    bool keep = !(cv[n] > thf);
    const float* src = keep ? out0 : outb;
    for (int c = 0; c < 100; ++c) out[n*100 + c] = src[n*100 + c];
}

// ----------------- launch -----------------
static float* sym(const void* symbol)
{
    void* p = nullptr;
    cudaGetSymbolAddress(&p, symbol);
    return (float*)p;
}

extern "C" void kernel_launch(void* const* d_in, const int* in_sizes, int n_in,
                              void* d_out, int out_size)
{
    const float* x    = (const float*)d_in[0];
    const int*   gt   = (const int*)  d_in[1];
    const float* u    = (const float*)d_in[2];
    const int*   flag = (const int*)  d_in[3];
    const float* w1 = (const float*)d_in[4];  const float* b1 = (const float*)d_in[5];
    const float* w2 = (const float*)d_in[6];  const float* b2 = (const float*)d_in[7];
    const float* w3 = (const float*)d_in[8];  const float* b3 = (const float*)d_in[9];
    const float* w4 = (const float*)d_in[10]; const float* b4 = (const float*)d_in[11];
    const float* w5 = (const float*)d_in[12]; const float* b5 = (const float*)d_in[13];
    const float* w6 = (const float*)d_in[14]; const float* b6 = (const float*)d_in[15];
    const float* w7 = (const float*)d_in[16]; const float* b7 = (const float*)d_in[17];
    const float* wc = (const float*)d_in[18]; const float* bc = (const float*)d_in[19];
    float* out = (float*)d_out;

    float* c1   = sym(d_c1);   float* l1   = sym(d_l1);
    float* c2   = sym(d_c2);   float* l2   = sym(d_l2);
    float* c3   = sym(d_c3);   float* c4   = sym(d_c4);   float* c5   = sym(d_c5);
    float* feat = sym(d_feat);
    float* h1   = sym(d_h1);   float* h2   = sym(d_h2);   float* out0 = sym(d_out0);
    float* g2   = sym(d_g2);   float* g1   = sym(d_g1);
    float* smv  = sym(d_sm);   float* mask = sym(d_mask);
    float* featm= sym(d_featm);float* h1b  = sym(d_h1b);  float* h2b  = sym(d_h2b);
    float* outb = sym(d_outb); float* clsb = sym(d_clsb); float* clsa = sym(d_clsa);
    float* w6r  = sym(d_w6r);  float* w7t  = sym(d_w7t);  float* part = sym(d_part);

    const int MN = BATCH*4096;

    cudaFuncSetAttribute(conv_f2b<3,227,227,96,96,11,11,4,0,55,55,1,96>,   cudaFuncAttributeMaxDynamicSharedMemorySize, SM_CONV(96));
    cudaFuncSetAttribute(conv_f2b<48,27,27,128,256,5,5,1,2,27,27,2,128>,   cudaFuncAttributeMaxDynamicSharedMemorySize, SM_CONV(128));
    cudaFuncSetAttribute(conv_f2b<256,13,13,384,384,3,3,1,1,13,13,1,128>,  cudaFuncAttributeMaxDynamicSharedMemorySize, SM_CONV(128));
    cudaFuncSetAttribute(conv_f2b<192,13,13,192,384,3,3,1,1,13,13,2,96>,   cudaFuncAttributeMaxDynamicSharedMemorySize, SM_CONV(96));
    cudaFuncSetAttribute(conv_f2b<192,13,13,128,256,3,3,1,1,13,13,2,128>,  cudaFuncAttributeMaxDynamicSharedMemorySize, SM_CONV(128));
    cudaFuncSetAttribute(fc_f2b, cudaFuncAttributeMaxDynamicSharedMemorySize, SM_FC);

    // ---- prep: folded w6 (gradient shortcut) + transposed w7 (nt-form grad GEMM) ----
    w6fold_k<<<(4096*36 + 255)/256, 256>>>(w6, w6r);
    transpose_k<<<dim3(128,128), dim3(32,8)>>>(w7, w7t);

    // ---- feature extractor ----
    conv_f2b<3,227,227,96,96,11,11,4,0,55,55,1,96><<<dim3(3025,1,1),256,SM_CONV(96)>>>(x, w1, b1, c1, 57.6f);
    poollrn_kernel<96,55,27><<<BATCH*27,256>>>(c1, l1);
    conv_f2b<48,27,27,128,256,5,5,1,2,27,27,2,128><<<dim3(729,1,2),256,SM_CONV(128)>>>(l1, w2, b2, c2, 1.f);
    poollrn_kernel<256,27,13><<<BATCH*13,256>>>(c2, l2);
    conv_f2b<256,13,13,384,384,3,3,1,1,13,13,1,128><<<dim3(169,3,1),256,SM_CONV(128)>>>(l2, w3, b3, c3, 1.f);
    conv_f2b<192,13,13,192,384,3,3,1,1,13,13,2,96><<<dim3(169,2,2),256,SM_CONV(96)>>>(c3, w4, b4, c4, 1.f);
    conv_f2b<192,13,13,128,256,3,3,1,1,13,13,2,128><<<dim3(169,1,2),256,SM_CONV(128)>>>(c4, w5, b5, c5, 1.f);
    pool_kernel<256,13,6><<<4608,256>>>(c5, feat);

    // ---- head #1 (unmasked) ----
    fc_f2b<<<dim3(32,1,8),256,SM_FC>>>(feat, w6, part, 4096, 9216, 1152);
    reduce_k<<<2048,256>>>(part, b6, nullptr, h1, MN, 8, 1);
    fc_f2b<<<dim3(32,1,8),256,SM_FC>>>(h1, w7, part, 4096, 4096, 512);
    reduce_k<<<2048,256>>>(part, b7, nullptr, h2, MN, 8, 1);
    cls_kernel<<<dim3(128,13),256>>>(h2, wc, bc, out0);
    softgt_kernel<<<128,32>>>(out0, gt, clsb);

    // ---- analytic gradient of out[n,gt] wrt features (folded to spatial mean) ----
    g2m_kernel<<<2048,256>>>(h2, wc, gt, g2);
    fc_f2b<<<dim3(32,1,8),256,SM_FC>>>(g2, w7t, part, 4096, 4096, 512);
    reduce_k<<<2048,256>>>(part, nullptr, h1, g1, MN, 8, 0);
    smgemm_k<<<128,256>>>(g1, w6r, smv);

    // ---- RSC spatial mask ----
    mask_kernel<<<1,128>>>(smv, u, flag, mask);
    applymask_kernel<<<4608,256>>>(feat, mask, featm);

    // ---- head #2 (masked) ----
    fc_f2b<<<dim3(32,1,8),256,SM_FC>>>(featm, w6, part, 4096, 9216, 1152);
    reduce_k<<<2048,256>>>(part, b6, nullptr, h1b, MN, 8, 1);
    fc_f2b<<<dim3(32,1,8),256,SM_FC>>>(h1b, w7, part, 4096, 4096, 512);
    reduce_k<<<2048,256>>>(part, b7, nullptr, h2b, MN, 8, 1);
    cls_kernel<<<dim3(128,13),256>>>(h2b, wc, bc, outb);
    softgt_kernel<<<128,32>>>(outb, gt, clsa);

    // ---- keep decision + final per-row select ----
    keepsel_kernel<<<1,128>>>(clsb, clsa, out0, outb, out);

    (void)in_sizes; (void)n_in; (void)out_size;
}

// round 6
// speedup vs baseline: 1.1757x; 1.0361x over previous
#include <cuda_runtime.h>
#include <math.h>
#include <stdint.h>

#define BATCH 128

// ----------------- scratch buffers -----------------
__device__ float d_c1[BATCH*96*55*55];
__device__ float d_l1[BATCH*96*27*27];
__device__ float d_c2[BATCH*256*27*27];
__device__ float d_l2[BATCH*256*13*13];
__device__ float d_c3[BATCH*384*13*13];
__device__ float d_c4[BATCH*384*13*13];
__device__ float d_c5[BATCH*256*13*13];
__device__ float d_feat[BATCH*9216];
__device__ float d_h1[BATCH*4096];
__device__ float d_h2[BATCH*4096];
__device__ float d_out0[BATCH*100];
__device__ float d_g2[BATCH*4096];
__device__ float d_g1[BATCH*4096];
__device__ float d_sm[BATCH*36];
__device__ float d_mask[BATCH*36];
__device__ float d_featm[BATCH*9216];
__device__ float d_h1b[BATCH*4096];
__device__ float d_h2b[BATCH*4096];
__device__ float d_outb[BATCH*100];
__device__ float d_clsb[BATCH];
__device__ float d_clsa[BATCH];
__device__ float d_w6r[4096*36];
__device__ float d_part[8*BATCH*4096];

// ----------------- f32x2 helpers -----------------
__device__ __forceinline__ unsigned long long pack2(float a, float b) {
    unsigned long long r;
    asm("mov.b64 %0, {%1, %2};" : "=l"(r) : "r"(__float_as_uint(a)), "r"(__float_as_uint(b)));
    return r;
}
__device__ __forceinline__ void fma2(unsigned long long& d, unsigned long long a, unsigned long long b) {
    asm("fma.rn.f32x2 %0, %1, %2, %0;" : "+l"(d) : "l"(a), "l"(b));
}
__device__ __forceinline__ float2 unpack2(unsigned long long v) {
    unsigned lo, hi;
    asm("mov.b64 {%0, %1}, %2;" : "=r"(lo), "=r"(hi) : "l"(v));
    float2 f; f.x = __uint_as_float(lo); f.y = __uint_as_float(hi); return f;
}

// ----------------- implicit-GEMM conv, f32x2, double-buffered (round-2 core) -----------------
// Tile: MT(oc) x 128(pixels) x 16(K). 256 threads. micro: (MT/16) x 8 (4 float2 pairs).
template<int CING, int HH, int WW, int COUTG, int COUTT, int KH, int KW,
         int STR, int PAD, int OH, int OW, int GROUPS, int MT>
__global__ __launch_bounds__(256, 2)
void conv_f2(const float* __restrict__ x, const float* __restrict__ w,
             const float* __restrict__ bias, float* __restrict__ out, float scale)
{
    constexpr int K    = CING*KH*KW;
    constexpr int CINT = CING*GROUPS;
    constexpr int OHW  = OH*OW;
    constexpr int MI   = MT/16;
    constexpr int AS   = MT + 4;
    constexpr int NCH  = (K + 15)/16;

    const int g    = blockIdx.z;
    const int pix0 = blockIdx.x * 128;
    const int m0   = blockIdx.y * MT;

    __shared__ __align__(16) float As[2][16][AS];
    __shared__ __align__(16) float Bs[2][16][132];

    const int t  = threadIdx.x;
    const int tx = t & 15, ty = t >> 4;
    const int lk = t & 15, lr = t >> 4;

    // per-pixel decode: base address + kh/kw validity bitmasks (improved loader)
    int pbase[8], vm[8];
    #pragma unroll
    for (int p = 0; p < 8; ++p) {
        int pix = pix0 + lr + p*16;
        int n   = pix / OHW; int rem = pix - n*OHW;
        int oh  = rem / OW;  int ow  = rem - oh*OW;
        int ihb = oh*STR - PAD, iwb = ow*STR - PAD;
        pbase[p] = (n*CINT + g*CING)*HH*WW + ihb*WW + iwb;
        int m1 = 0, m2 = 0;
        #pragma unroll
        for (int kh = 0; kh < KH; ++kh) if ((unsigned)(ihb + kh) < (unsigned)HH) m1 |= 1 << kh;
        #pragma unroll
        for (int kw = 0; kw < KW; ++kw) if ((unsigned)(iwb + kw) < (unsigned)WW) m2 |= 1 << kw;
        vm[p] = m1 | (m2 << 16);
    }

    const float* wbase = w + (size_t)(g*COUTG + m0)*K;

    float ra[MI], rb[8];

    auto loadA = [&](int k0) {
        int kg = k0 + lk; bool kv = kg < K;
        #pragma unroll
        for (int p = 0; p < MI; ++p)
            ra[p] = kv ? wbase[(lr + p*16)*K + kg] : 0.f;
    };
    auto loadB = [&](int k0) {
        int kg = k0 + lk; bool kv = kg < K;
        int kc = kv ? kg : 0;
        int ic = kc / (KH*KW);
        int r2 = kc - ic*(KH*KW);
        int kh = r2 / KW, kw = r2 - kh*KW;
        int koff = ic*HH*WW + kh*WW + kw;
        #pragma unroll
        for (int p = 0; p < 8; ++p) {
            bool ok;
            if (PAD == 0) ok = kv;
            else ok = kv && ((vm[p] >> kh) & 1) && ((vm[p] >> (16 + kw)) & 1);
            rb[p] = ok ? x[pbase[p] + koff] * scale : 0.f;
        }
    };
    auto stTile = [&](int buf) {
        #pragma unroll
        for (int p = 0; p < MI; ++p) As[buf][lk][lr + p*16] = ra[p];
        #pragma unroll
        for (int p = 0; p < 8;  ++p) Bs[buf][lk][lr + p*16] = rb[p];
    };

    unsigned long long acc[MI][4];
    #pragma unroll
    for (int i = 0; i < MI; ++i)
        #pragma unroll
        for (int j = 0; j < 4; ++j) acc[i][j] = 0ull;

    loadA(0); loadB(0); stTile(0);
    __syncthreads();

    for (int c = 0; c < NCH; ++c) {
        int buf = c & 1;
        if (c + 1 < NCH) { loadA((c+1)*16); loadB((c+1)*16); }
        #pragma unroll
        for (int kk = 0; kk < 16; ++kk) {
            unsigned long long b2[4];
            #pragma unroll
            for (int j = 0; j < 4; ++j)
                b2[j] = *(const unsigned long long*)&Bs[buf][kk][tx*2 + j*32];
            #pragma unroll
            for (int i = 0; i < MI; ++i) {
                float av = As[buf][kk][ty + i*16];
                unsigned long long a2 = pack2(av, av);
                #pragma unroll
                for (int j = 0; j < 4; ++j) fma2(acc[i][j], a2, b2[j]);
            }
        }
        if (c + 1 < NCH) stTile(buf ^ 1);
        __syncthreads();
    }

    #pragma unroll
    for (int i = 0; i < MI; ++i) {
        int m = m0 + ty + i*16;
        float bv = bias[g*COUTG + m];
        #pragma unroll
        for (int j = 0; j < 4; ++j) {
            float2 v = unpack2(acc[i][j]);
            int pix = pix0 + tx*2 + j*32;
            int n0_ = pix / OHW;       int r0_ = pix - n0_*OHW;
            int n1_ = (pix+1) / OHW;   int r1_ = (pix+1) - n1_*OHW;
            out[((size_t)(n0_*COUTT + g*COUTG + m))*OHW + r0_] = fmaxf(v.x + bv, 0.f);
            out[((size_t)(n1_*COUTT + g*COUTG + m))*OHW + r1_] = fmaxf(v.y + bv, 0.f);
        }
    }
}

// ----------------- split-K GEMM, f32x2, 64x64 tiles (round-2 core) -----------------
template<int TRANSB>
__global__ __launch_bounds__(256, 2)
void gemm_f2(const float* __restrict__ A, const float* __restrict__ B,
             float* __restrict__ part, int M, int N, int K, int Kc)
{
    __shared__ __align__(16) float As[2][16][68];
    __shared__ __align__(16) float Bs[2][16][68];
    const int m0 = blockIdx.y*64, n0 = blockIdx.x*64;
    const int z  = blockIdx.z;
    const int kb = z*Kc;
    const int ke = min(K, kb + Kc);
    const int t = threadIdx.x, tx = t & 15, ty = t >> 4;
    const int lk = t & 15, lr = t >> 4;
    const int lr2 = t & 63, lk2 = t >> 6;

    float ra[4], rbv[4];
    auto loadA = [&](int k0) {
        int kg = k0 + lk; bool kv = kg < ke;
        #pragma unroll
        for (int p = 0; p < 4; ++p)
            ra[p] = kv ? A[(size_t)(m0 + lr + p*16)*K + kg] : 0.f;
    };
    auto loadB = [&](int k0) {
        if (TRANSB) {
            int kg = k0 + lk; bool kv = kg < ke;
            #pragma unroll
            for (int p = 0; p < 4; ++p)
                rbv[p] = kv ? B[(size_t)(n0 + lr + p*16)*K + kg] : 0.f;
        } else {
            #pragma unroll
            for (int p = 0; p < 4; ++p) {
                int kg = k0 + lk2 + p*4;
                rbv[p] = (kg < ke) ? B[(size_t)kg*N + n0 + lr2] : 0.f;
            }
        }
    };
    auto stT = [&](int buf) {
        #pragma unroll
        for (int p = 0; p < 4; ++p) As[buf][lk][lr + p*16] = ra[p];
        if (TRANSB) {
            #pragma unroll
            for (int p = 0; p < 4; ++p) Bs[buf][lk][lr + p*16] = rbv[p];
        } else {
            #pragma unroll
            for (int p = 0; p < 4; ++p) Bs[buf][lk2 + p*4][lr2] = rbv[p];
        }
    };

    unsigned long long acc[4][2];
    #pragma unroll
    for (int i = 0; i < 4; ++i) { acc[i][0] = 0ull; acc[i][1] = 0ull; }

    const int nch = (ke - kb + 15)/16;
    loadA(kb); loadB(kb); stT(0);
    __syncthreads();

    for (int c = 0; c < nch; ++c) {
        int buf = c & 1;
        if (c + 1 < nch) { loadA(kb + (c+1)*16); loadB(kb + (c+1)*16); }
        #pragma unroll
        for (int kk = 0; kk < 16; ++kk) {
            unsigned long long b2[2];
            #pragma unroll
            for (int j = 0; j < 2; ++j)
                b2[j] = *(const unsigned long long*)&Bs[buf][kk][tx*2 + j*32];
            #pragma unroll
            for (int i = 0; i < 4; ++i) {
                float av = As[buf][kk][ty + i*16];
                unsigned long long a2 = pack2(av, av);
                #pragma unroll
                for (int j = 0; j < 2; ++j) fma2(acc[i][j], a2, b2[j]);
            }
        }
        if (c + 1 < nch) stT(buf ^ 1);
        __syncthreads();
    }

    #pragma unroll
    for (int i = 0; i < 4; ++i) {
        int m = m0 + ty + i*16;
        #pragma unroll
        for (int j = 0; j < 2; ++j) {
            float2 v = unpack2(acc[i][j]);
            int n = n0 + tx*2 + j*32;
            *(float2*)&part[((size_t)z*M + m)*N + n] = v;
        }
    }
}

// ----------------- split-K reduce + bias/relu/mask epilogue (N=4096) -----------------
__global__ void reduce_k(const float* __restrict__ part, const float* __restrict__ bias,
                         const float* __restrict__ maskref, float* __restrict__ C,
                         int MN, int S, int doRelu)
{
    int i = blockIdx.x*256 + threadIdx.x;
    if (i >= MN) return;
    float s = 0.f;
    for (int z = 0; z < S; ++z) s += part[(size_t)z*MN + i];
    if (bias) s += bias[i & 4095];
    if (doRelu) s = fmaxf(s, 0.f);
    if (maskref) s = (maskref[i] > 0.f) ? s : 0.f;
    C[i] = s;
}

// ----------------- fused maxpool(3,2) + LRN(n=5) : block = (n, oy) -----------------
template<int C, int HI, int HO>
__global__ void poollrn_kernel(const float* __restrict__ in, float* __restrict__ out)
{
    __shared__ float pl[C*HO];
    int b = blockIdx.x;
    int n = b / HO, oy = b % HO;
    for (int idx = threadIdx.x; idx < C*HO; idx += 256) {
        int c = idx / HO, ox = idx - c*HO;
        const float* p = in + ((size_t)(n*C + c)*HI + oy*2)*HI + ox*2;
        float m = -3.4e38f;
        #pragma unroll
        for (int a = 0; a < 3; ++a)
            #pragma unroll
            for (int bq = 0; bq < 3; ++bq)
                m = fmaxf(m, p[a*HI + bq]);
        pl[idx] = m;
    }
    __syncthreads();
    for (int idx = threadIdx.x; idx < C*HO; idx += 256) {
        int c = idx / HO, ox = idx - c*HO;
        float sum = 0.f;
        #pragma unroll
        for (int d = -2; d <= 2; ++d) {
            int cc = c + d;
            if (cc >= 0 && cc < C) {
                float v = pl[cc*HO + ox];
                sum = fmaf(v, v, sum);
            }
        }
        float r = rsqrtf(fmaf(2e-5f, sum, 1.0f));
        out[((size_t)(n*C + c)*HO + oy)*HO + ox] = pl[idx] * r * sqrtf(r);
    }
}

// ----------------- maxpool 3x3 stride 2 (final 13->6) -----------------
template<int C, int HI, int HO>
__global__ void pool_kernel(const float* __restrict__ in, float* __restrict__ out)
{
    constexpr int TOT = BATCH*C*HO*HO;
    int idx = blockIdx.x*256 + threadIdx.x;
    if (idx >= TOT) return;
    int ox = idx % HO;
    int tq = idx / HO;
    int oy = tq % HO;
    int nc = tq / HO;
    const float* p = in + ((size_t)nc*HI + oy*2)*HI + ox*2;
    float m = -3.4e38f;
    #pragma unroll
    for (int a = 0; a < 3; ++a)
        #pragma unroll
        for (int b = 0; b < 3; ++b)
            m = fmaxf(m, p[a*HI + b]);
    out[idx] = m;
}

// ----------------- fold w6 over channels -----------------
__global__ void w6fold_k(const float* __restrict__ w6, float* __restrict__ w6r)
{
    int i = blockIdx.x*256 + threadIdx.x;
    if (i >= 4096*36) return;
    int j = i / 36, s = i - j*36;
    const float* p = w6 + (size_t)j*9216 + s;
    float acc = 0.f;
    for (int c = 0; c < 256; ++c) acc += p[c*36];
    w6r[i] = acc * (1.f/256.f);
}

// ----------------- sm[n,s] = g1[n,:] . w6r[:,s] -----------------
__global__ void smgemm_k(const float* __restrict__ g1, const float* __restrict__ w6r,
                         float* __restrict__ sm)
{
    __shared__ float gs[4096];
    int n = blockIdx.x, t = threadIdx.x;
    for (int k = t; k < 4096; k += 256) gs[k] = g1[n*4096 + k];
    __syncthreads();
    int warp = t >> 5, lane = t & 31;
    for (int s = warp; s < 36; s += 8) {
        float acc = 0.f;
        for (int k = lane; k < 4096; k += 32) acc += gs[k] * w6r[k*36 + s];
        #pragma unroll
        for (int o = 16; o; o >>= 1) acc += __shfl_xor_sync(0xffffffffu, acc, o);
        if (lane == 0) sm[n*36 + s] = acc;
    }
}

// ----------------- classifier dot -----------------
__global__ void cls_kernel(const float* __restrict__ h, const float* __restrict__ wc,
                           const float* __restrict__ bc, float* __restrict__ out)
{
    int n = blockIdx.x;
    int warp = threadIdx.x >> 5, lane = threadIdx.x & 31;
    int c = blockIdx.y*8 + warp;
    if (c >= 100) return;
    const float4* hp = (const float4*)(h + n*4096);
    const float4* wp = (const float4*)(wc + c*4096);
    float s = 0.f;
    for (int k = lane; k < 1024; k += 32) {
        float4 a = hp[k], b = wp[k];
        s += a.x*b.x + a.y*b.y + a.z*b.z + a.w*b.w;
    }
    #pragma unroll
    for (int o = 16; o; o >>= 1) s += __shfl_xor_sync(0xffffffffu, s, o);
    if (lane == 0) out[n*100 + c] = s + bc[c];
}

// ----------------- softmax probability at gt -----------------
__global__ void softgt_kernel(const float* __restrict__ logits, const int* __restrict__ gt,
                              float* __restrict__ cls)
{
    int n = blockIdx.x;
    int lane = threadIdx.x;
    float m = -3.4e38f;
    for (int c = lane; c < 100; c += 32) m = fmaxf(m, logits[n*100 + c]);
    #pragma unroll
    for (int o = 16; o; o >>= 1) m = fmaxf(m, __shfl_xor_sync(0xffffffffu, m, o));
    float s = 0.f;
    for (int c = lane; c < 100; c += 32) s += expf(logits[n*100 + c] - m);
    #pragma unroll
    for (int o = 16; o; o >>= 1) s += __shfl_xor_sync(0xffffffffu, s, o);
    if (lane == 0) cls[n] = expf(logits[n*100 + gt[n]] - m) / s;
}

// ----------------- g2 = relu'(h2) * wc[gt] -----------------
__global__ void g2m_kernel(const float* __restrict__ h2, const float* __restrict__ wc,
                           const int* __restrict__ gt, float* __restrict__ g2)
{
    int idx = blockIdx.x*256 + threadIdx.x;
    if (idx >= BATCH*4096) return;
    int n = idx >> 12, j = idx & 4095;
    g2[idx] = (h2[idx] > 0.f) ? wc[gt[n]*4096 + j] : 0.f;
}

// ----------------- per-sample RSC spatial mask -----------------
__global__ void mask_kernel(const float* __restrict__ sm, const float* __restrict__ u,
                            const int* __restrict__ flag, float* __restrict__ mask)
{
    int n = threadIdx.x;
    if (n >= BATCH) return;
    if (*flag == 0) {
        for (int s = 0; s < 36; ++s) mask[n*36 + s] = 1.f;
        return;
    }
    float v[36], tmp[36], sc[36], mk[36];
    for (int s = 0; s < 36; ++s) { v[s] = sm[n*36 + s]; tmp[s] = v[s]; mk[s] = 1.f; }
    float th = 0.f;
    for (int it = 0; it < 13; ++it) {
        int bi = 0; float bv = tmp[0];
        for (int s = 1; s < 36; ++s) if (tmp[s] > bv) { bv = tmp[s]; bi = s; }
        th = bv; tmp[bi] = -3.4e38f;
    }
    for (int s = 0; s < 36; ++s) sc[s] = (v[s] >= th) ? u[n*36 + s] : -1.f;
    for (int it = 0; it < 12; ++it) {
        int bi = 0; float bv = sc[0];
        for (int s = 1; s < 36; ++s) if (sc[s] > bv) { bv = sc[s]; bi = s; }
        mk[bi] = 0.f; sc[bi] = -2.f;
    }
    for (int s = 0; s < 36; ++s) mask[n*36 + s] = mk[s];
}

// ----------------- apply spatial mask -----------------
__global__ void applymask_kernel(const float* __restrict__ f, const float* __restrict__ mask,
                                 float* __restrict__ o)
{
    int i = blockIdx.x*256 + threadIdx.x;
    if (i >= BATCH*9216) return;
    int n = i / 9216;
    int s = i % 36;
    o[i] = f[i] * mask[n*36 + s];
}

// ----------------- keep decision + per-row output select -----------------
__global__ void keepsel_kernel(const float* __restrict__ clsb, const float* __restrict__ clsa,
                               const float* __restrict__ out0, const float* __restrict__ outb,
                               float* __restrict__ out)
{
    __shared__ float cv[BATCH];
    __shared__ float thf;
    int n = threadIdx.x;
    cv[n] = fmaxf(clsb[n] - clsa[n] - 1e-4f, 0.f);
    __syncthreads();
    if (n == 0) {
        float tmp[BATCH];
        for (int i = 0; i < BATCH; ++i) tmp[i] = cv[i];
        float bv = 0.f;
        for (int it = 0; it < 44; ++it) {
            int bi = 0; bv = tmp[0];
            for (int i = 1; i < BATCH; ++i) if (tmp[i] > bv) { bv = tmp[i]; bi = i; }
            tmp[bi] = -3.4e38f;
        }
        thf = bv;
    }
    __syncthreads();
    bool keep = !(cv[n] > thf);
    const float* src = keep ? out0 : outb;
    for (int c = 0; c < 100; ++c) out[n*100 + c] = src[n*100 + c];
}

// ----------------- launch -----------------
static float* sym(const void* symbol)
{
    void* p = nullptr;
    cudaGetSymbolAddress(&p, symbol);
    return (float*)p;
}

extern "C" void kernel_launch(void* const* d_in, const int* in_sizes, int n_in,
                              void* d_out, int out_size)
{
    const float* x    = (const float*)d_in[0];
    const int*   gt   = (const int*)  d_in[1];
    const float* u    = (const float*)d_in[2];
    const int*   flag = (const int*)  d_in[3];
    const float* w1 = (const float*)d_in[4];  const float* b1 = (const float*)d_in[5];
    const float* w2 = (const float*)d_in[6];  const float* b2 = (const float*)d_in[7];
    const float* w3 = (const float*)d_in[8];  const float* b3 = (const float*)d_in[9];
    const float* w4 = (const float*)d_in[10]; const float* b4 = (const float*)d_in[11];
    const float* w5 = (const float*)d_in[12]; const float* b5 = (const float*)d_in[13];
    const float* w6 = (const float*)d_in[14]; const float* b6 = (const float*)d_in[15];
    const float* w7 = (const float*)d_in[16]; const float* b7 = (const float*)d_in[17];
    const float* wc = (const float*)d_in[18]; const float* bc = (const float*)d_in[19];
    float* out = (float*)d_out;

    float* c1   = sym(d_c1);   float* l1   = sym(d_l1);
    float* c2   = sym(d_c2);   float* l2   = sym(d_l2);
    float* c3   = sym(d_c3);   float* c4   = sym(d_c4);   float* c5   = sym(d_c5);
    float* feat = sym(d_feat);
    float* h1   = sym(d_h1);   float* h2   = sym(d_h2);   float* out0 = sym(d_out0);
    float* g2   = sym(d_g2);   float* g1   = sym(d_g1);
    float* smv  = sym(d_sm);   float* mask = sym(d_mask);
    float* featm= sym(d_featm);float* h1b  = sym(d_h1b);  float* h2b  = sym(d_h2b);
    float* outb = sym(d_outb); float* clsb = sym(d_clsb); float* clsa = sym(d_clsa);
    float* w6r  = sym(d_w6r);  float* part = sym(d_part);

    const int MN = BATCH*4096;

    // ---- prep: folded w6 (gradient spatial-mean shortcut) ----
    w6fold_k<<<(4096*36 + 255)/256, 256>>>(w6, w6r);

    // ---- feature extractor ----
    conv_f2<3,227,227,96,96,11,11,4,0,55,55,1,96><<<dim3(3025,1,1),256>>>(x, w1, b1, c1, 57.6f);
    poollrn_kernel<96,55,27><<<BATCH*27,256>>>(c1, l1);
    conv_f2<48,27,27,128,256,5,5,1,2,27,27,2,128><<<dim3(729,1,2),256>>>(l1, w2, b2, c2, 1.f);
    poollrn_kernel<256,27,13><<<BATCH*13,256>>>(c2, l2);
    conv_f2<256,13,13,384,384,3,3,1,1,13,13,1,128><<<dim3(169,3,1),256>>>(l2, w3, b3, c3, 1.f);
    conv_f2<192,13,13,192,384,3,3,1,1,13,13,2,96><<<dim3(169,2,2),256>>>(c3, w4, b4, c4, 1.f);
    conv_f2<192,13,13,128,256,3,3,1,1,13,13,2,128><<<dim3(169,1,2),256>>>(c4, w5, b5, c5, 1.f);
    pool_kernel<256,13,6><<<4608,256>>>(c5, feat);

    // ---- head #1 (unmasked) ----
    gemm_f2<1><<<dim3(64,2,8),256>>>(feat, w6, part, 128, 4096, 9216, 1152);
    reduce_k<<<2048,256>>>(part, b6, nullptr, h1, MN, 8, 1);
    gemm_f2<1><<<dim3(64,2,8),256>>>(h1, w7, part, 128, 4096, 4096, 512);
    reduce_k<<<2048,256>>>(part, b7, nullptr, h2, MN, 8, 1);
    cls_kernel<<<dim3(128,13),256>>>(h2, wc, bc, out0);
    softgt_kernel<<<128,32>>>(out0, gt, clsb);

    // ---- analytic gradient of out[n,gt] wrt features (folded to spatial mean) ----
    g2m_kernel<<<2048,256>>>(h2, wc, gt, g2);
    gemm_f2<0><<<dim3(64,2,8),256>>>(g2, w7, part, 128, 4096, 4096, 512);
    reduce_k<<<2048,256>>>(part, nullptr, h1, g1, MN, 8, 0);
    smgemm_k<<<128,256>>>(g1, w6r, smv);

    // ---- RSC spatial mask ----
    mask_kernel<<<1,128>>>(smv, u, flag, mask);
    applymask_kernel<<<4608,256>>>(feat, mask, featm);

    // ---- head #2 (masked) ----
    gemm_f2<1><<<dim3(64,2,8),256>>>(featm, w6, part, 128, 4096, 9216, 1152);
    reduce_k<<<2048,256>>>(part, b6, nullptr, h1b, MN, 8, 1);
    gemm_f2<1><<<dim3(64,2,8),256>>>(h1b, w7, part, 128, 4096, 4096, 512);
    reduce_k<<<2048,256>>>(part, b7, nullptr, h2b, MN, 8, 1);
    cls_kernel<<<dim3(128,13),256>>>(h2b, wc, bc, outb);
    softgt_kernel<<<128,32>>>(outb, gt, clsa);

    // ---- keep decision + final per-row select (head #3 ≡ row-select of #1/#2) ----
    keepsel_kernel<<<1,128>>>(clsb, clsa, out0, outb, out);

    (void)in_sizes; (void)n_in; (void)out_size;
}